// round 3
// baseline (speedup 1.0000x reference)
#include <cuda_runtime.h>
#include <cuda_bf16.h>
#include <math.h>

// ---------------- problem constants ----------------
#define NN      65536
#define ROWS    16      // BATCH*CH
#define JLEV    5
#define QQ      8
#define CQ      32      // QQ*CH
#define TT      15
#define OUTN    16384   // NN/4
#define OUTCH   160     // JLEV*CQ

typedef unsigned long long ull;

// ---------------- wavelet filters ----------------
__constant__ float c_H0O[13] = {
  -0.00455690456024f, -0.00543947593727f,  0.01702522388155f,  0.02382538479492f,
  -0.10671180468666f,  0.01186609203379f,  0.56881042071212f,  0.75614564389252f,
   0.27529538466888f, -0.11720388769911f, -0.03887280126882f,  0.03466034684485f,
  -0.00388321199915f };
__constant__ float c_H1O[13] = {
  -0.00388321199915f, -0.03466034684485f, -0.03887280126882f,  0.11720388769911f,
   0.27529538466888f, -0.75614564389252f,  0.56881042071212f, -0.01186609203379f,
  -0.10671180468666f, -0.02382538479492f,  0.01702522388155f,  0.00543947593727f,
  -0.00455690456024f };
__constant__ float c_H0A[10] = {
   0.03516384f, 0.0f, -0.08832942f, 0.23389032f, 0.76027237f,
   0.58751830f, 0.0f, -0.11430184f, 0.0f, 0.0f };
__constant__ float c_H0B[10] = {
   0.0f, 0.0f, -0.11430184f, 0.0f, 0.58751830f,
   0.76027237f, 0.23389032f, -0.08832942f, 0.0f, 0.03516384f };
__constant__ float c_H1A[10] = {
   0.0f, 0.0f, -0.11430184f, 0.0f, 0.58751830f,
  -0.76027237f, 0.23389032f, 0.08832942f, 0.0f, -0.03516384f };
__constant__ float c_H1B[10] = {
  -0.03516384f, 0.0f, 0.08832942f, 0.23389032f, -0.76027237f,
   0.58751830f, 0.0f, -0.11430184f, 0.0f, 0.0f };

// ---------------- scratch: interleaved (r,i) bandpass ----------------
__device__ float2 g_bp[(size_t)JLEV * ROWS * NN];

// ---------------- packed f32x2 helpers ----------------
__device__ __forceinline__ ull pack2(float x, float y) {
  ull r; asm("mov.b64 %0, {%1, %2};" : "=l"(r) : "f"(x), "f"(y)); return r;
}
__device__ __forceinline__ void unpack2(ull v, float& x, float& y) {
  asm("mov.b64 {%0, %1}, %2;" : "=f"(x), "=f"(y) : "l"(v));
}
__device__ __forceinline__ ull ffma2(ull a, ull b, ull c) {
  ull d; asm("fma.rn.f32x2 %0, %1, %2, %3;" : "=l"(d) : "l"(a), "l"(b), "l"(c));
  return d;
}

// ---------------- kernel 1: undecimated dual-tree CWT ----------------
#define TILE_W 2048
#define HALO   80
#define EXT    (TILE_W + 2*HALO)   // 2208

template<int D, int M>
__device__ __forceinline__ void tree_level(
    const float* la, const float* lb,
    float* la_n, float* lb_n,
    float2* __restrict__ bp)
{
  const int PAD = (D * 9) / 2;
  for (int i = threadIdx.x; i < TILE_W; i += 256) {
    const int s = HALO + i;
    float ar = 0.f, ai = 0.f;
#pragma unroll
    for (int k = 0; k < 10; k++) {
      ar = fmaf(c_H1A[k], la[s + D*k - PAD], ar);
      ai = fmaf(c_H1B[k], lb[s + D*k - PAD], ai);
    }
    bp[i] = make_float2(ar, ai);
  }
  if (la_n != nullptr) {
    for (int i = threadIdx.x; i < TILE_W + 2*M; i += 256) {
      const int s = HALO - M + i;
      float a = 0.f, b = 0.f;
#pragma unroll
      for (int k = 0; k < 10; k++) {
        a = fmaf(c_H0A[k], la[s + D*k - PAD], a);
        b = fmaf(c_H0B[k], lb[s + D*k - PAD], b);
      }
      la_n[s] = a; lb_n[s] = b;
    }
  }
}

__global__ __launch_bounds__(256) void udtcwt_kernel(const float* __restrict__ x)
{
  __shared__ float sA[EXT], sB[EXT], sC[EXT], sD[EXT];
  const int row = blockIdx.y;
  const int t0  = blockIdx.x * TILE_W;
  const float* xr = x + (size_t)row * NN;

  for (int s = threadIdx.x; s < EXT; s += 256) {
    const int g = t0 - HALO + s;
    sA[s] = (g >= 0 && g < NN) ? xr[g] : 0.f;
  }
  __syncthreads();

  // level 0: 13-tap near_sym_b, both trees identical
  {
    float2* outp = g_bp + ((size_t)(0*ROWS + row)) * NN + t0;
    for (int i = threadIdx.x; i < TILE_W; i += 256) {
      const int s = HALO + i;
      float acc = 0.f;
#pragma unroll
      for (int k = 0; k < 13; k++) acc = fmaf(c_H1O[k], sA[s + k - 6], acc);
      outp[i] = make_float2(acc, acc);
    }
    for (int i = threadIdx.x; i < TILE_W + 2*68; i += 256) {
      const int s = HALO - 68 + i;
      float acc = 0.f;
#pragma unroll
      for (int k = 0; k < 13; k++) acc = fmaf(c_H0O[k], sA[s + k - 6], acc);
      sB[s] = acc;
    }
  }
  __syncthreads();

  tree_level<1, 63>(sB, sB, sC, sD, g_bp + ((size_t)(1*ROWS + row))*NN + t0);
  __syncthreads();
  tree_level<2, 54>(sC, sD, sA, sB, g_bp + ((size_t)(2*ROWS + row))*NN + t0);
  __syncthreads();
  tree_level<4, 36>(sA, sB, sC, sD, g_bp + ((size_t)(3*ROWS + row))*NN + t0);
  __syncthreads();
  tree_level<8, 0>(sC, sD, (float*)nullptr, (float*)nullptr,
                   g_bp + ((size_t)(4*ROWS + row))*NN + t0);
}

// ---------------- kernel 2: all scales, phase-decomposed ----------------
// out[n] = sum_{m=0}^{36} g[m] * u[4n + m - 18]   (two lowpass+::2 stages fused)
// u[t] = (sqrt(r^2+i^2)/2^{j/2} + beta)^sigmoid(root),  r/i = 15-tap dilated conv.
#define TOX    512
#define ULEN   (4*TOX + 33)      // 2081
#define UPAD   (4*TOX + 48)      // 2096
#define BPWC   2256              // worst-case D*SP over D in {1,2,4,8}

__global__ __launch_bounds__(256, 4) void scatter_all(
    const float* __restrict__ conv_w, const float* __restrict__ roots,
    const float* __restrict__ beta_p, float* __restrict__ out)
{
  __shared__ float2 s_bp[BPWC];
  __shared__ float  s_u[UPAD];
  __shared__ ull    s_w2[QQ * TT];
  __shared__ float  s_g[40];
  __shared__ float  s_alpha[QQ];

  const int j   = blockIdx.z;
  const int ld  = (j <= 1) ? 0 : (j - 1);     // log2(dilation)
  const int D   = 1 << ld;
  const int row = blockIdx.y;                  // b*CH + c
  const int b   = row >> 2, c = row & 3;
  const int o0  = blockIdx.x * TOX;
  const float inv_scale = exp2f(-0.5f * (float)j);
  const float beta = beta_p[0];

  // runtime phase geometry
  const int SU   = (ULEN + D - 1) >> ld;       // u's per phase
  const int CP   = (SU + 3) >> 2;              // 4-u chunks per phase
  const int chunks = D * CP;
  const int SLEN = 4 * CP + 18;
  const int SP   = (SLEN + 1) & ~1;            // even stride (16B-aligned phases)
  const int SPH  = SP >> 1;                    // in float4 units

  const int tmin = 4 * o0 - 18;
  const int pmin = tmin - 7 * D;

  const float2* bp = g_bp + ((size_t)(j * ROWS + row)) * NN;

  // ---- fill phase-separated bp tile ----
  for (int i = threadIdx.x; i < D * SP; i += 256) {
    const int p = i & (D - 1), s = i >> ld;
    const int gi = pmin + i;
    s_bp[p * SP + s] = (gi >= 0 && gi < NN) ? bp[gi] : make_float2(0.f, 0.f);
  }
  if (threadIdx.x < 37) {                      // composite /4 downsample filter
    const int m = threadIdx.x;
    float acc = 0.f;
    for (int k = 0; k < 13; k++) {
      const int kp = m - 2 * k;
      if (kp >= 0 && kp < 13) acc += c_H0O[k] * c_H0O[kp];
    }
    s_g[m] = acc;
  }
  for (int i = threadIdx.x; i < QQ * TT; i += 256) {
    const int q = i / TT, k = i % TT;
    const float wv = conv_w[(size_t)(j * CQ + c * QQ + q) * TT + k];
    s_w2[i] = pack2(wv, wv);
  }
  if (threadIdx.x < QQ) {
    const float rt = roots[j * CQ + c * QQ + threadIdx.x];
    s_alpha[threadIdx.x] = 1.f / (1.f + __expf(-rt));
  }
  __syncthreads();

  const int rot9 = (ld == 0) ? ((threadIdx.x >> 2) & 1) : 0;  // D=1 bank fix
  const int rot11 = (threadIdx.x >> 2) & 1;                    // downsample fix

  for (int q = 0; q < QQ; q++) {
    const ull* wq = s_w2 + q * TT;
    const float alpha = s_alpha[q];

    // ---- u computation: 4 consecutive-in-phase u's per chunk ----
    for (int m = threadIdx.x; m < chunks; m += 256) {
      const int p = m & (D - 1), cc = m >> ld;
      const float4* vp = reinterpret_cast<const float4*>(s_bp) + p * SPH + 2 * cc;
      ull v[18];
#pragma unroll
      for (int t0 = 0; t0 < 9; t0++) {
        int t = t0 + rot9; if (t >= 9) t -= 9;
        const float4 qv = vp[t];
        v[2*t]   = pack2(qv.x, qv.y);
        v[2*t+1] = pack2(qv.z, qv.w);
      }
      ull acc0 = pack2(0.f, 0.f), acc1 = acc0, acc2 = acc0, acc3 = acc0;
#pragma unroll
      for (int k = 0; k < TT; k++) {
        const ull wk = wq[k];
        acc0 = ffma2(wk, v[k],     acc0);
        acc1 = ffma2(wk, v[k + 1], acc1);
        acc2 = ffma2(wk, v[k + 2], acc2);
        acc3 = ffma2(wk, v[k + 3], acc3);
      }
      const int s0 = 4 * cc;
      ull accs[4] = {acc0, acc1, acc2, acc3};
#pragma unroll
      for (int r = 0; r < 4; r++) {
        const int ui = p + D * (s0 + r);
        if (ui < ULEN) {
          float rr, ii; unpack2(accs[r], rr, ii);
          const int t = tmin + ui;
          float u = 0.f;
          if (t >= 0 && t < NN) {
            const float hyp = sqrtf(fmaf(rr, rr, ii * ii)) * inv_scale;
            u = exp2f(alpha * __log2f(hyp + beta));
          }
          s_u[ui] = u;
        }
      }
    }
    __syncthreads();

    // ---- fused 37-tap stride-4 downsample: 2 outputs/thread ----
    {
      const float4* su4 = reinterpret_cast<const float4*>(s_u) + 2 * threadIdx.x;
      float a[44];
#pragma unroll
      for (int tt = 0; tt < 11; tt++) {
        int t = tt + rot11; if (t >= 11) t -= 11;
        const float4 qv = su4[t];
        a[4*t] = qv.x; a[4*t+1] = qv.y; a[4*t+2] = qv.z; a[4*t+3] = qv.w;
      }
      float2 o;
      float acc0 = 0.f, acc1 = 0.f;
#pragma unroll
      for (int mm = 0; mm < 37; mm++) {
        acc0 = fmaf(s_g[mm], a[mm],     acc0);
        acc1 = fmaf(s_g[mm], a[mm + 4], acc1);
      }
      o.x = acc0; o.y = acc1;
      float* dst = out + ((size_t)(b * OUTCH + j * CQ + c * QQ + q)) * OUTN
                       + o0 + 2 * threadIdx.x;
      *reinterpret_cast<float2*>(dst) = o;
    }
    __syncthreads();
  }
}

// ---------------- launch ----------------
extern "C" void kernel_launch(void* const* d_in, const int* in_sizes, int n_in,
                              void* d_out, int out_size)
{
  const float* x      = (const float*)d_in[0];
  const float* conv_w = (const float*)d_in[1];
  const float* roots  = (const float*)d_in[2];
  const float* beta   = (const float*)d_in[3];
  float* out = (float*)d_out;

  dim3 gW(NN / TILE_W, ROWS);                 // 32 x 16
  udtcwt_kernel<<<gW, 256>>>(x);

  dim3 gS(OUTN / TOX, ROWS, JLEV);            // 32 x 16 x 5 = 2560 CTAs
  scatter_all<<<gS, 256>>>(conv_w, roots, beta, out);
}

// round 4
// speedup vs baseline: 4.7672x; 4.7672x over previous
#include <cuda_runtime.h>
#include <cuda_bf16.h>
#include <math.h>

// ---------------- problem constants ----------------
#define NN      65536
#define ROWS    16      // BATCH*CH
#define JLEV    5
#define QQ      8
#define CQ      32      // QQ*CH
#define TT      15
#define OUTN    16384   // NN/4
#define OUTCH   160     // JLEV*CQ

typedef unsigned long long ull;

// ---------------- wavelet filters ----------------
__constant__ float c_H0O[13] = {
  -0.00455690456024f, -0.00543947593727f,  0.01702522388155f,  0.02382538479492f,
  -0.10671180468666f,  0.01186609203379f,  0.56881042071212f,  0.75614564389252f,
   0.27529538466888f, -0.11720388769911f, -0.03887280126882f,  0.03466034684485f,
  -0.00388321199915f };
__constant__ float c_H1O[13] = {
  -0.00388321199915f, -0.03466034684485f, -0.03887280126882f,  0.11720388769911f,
   0.27529538466888f, -0.75614564389252f,  0.56881042071212f, -0.01186609203379f,
  -0.10671180468666f, -0.02382538479492f,  0.01702522388155f,  0.00543947593727f,
  -0.00455690456024f };
__constant__ float c_H0A[10] = {
   0.03516384f, 0.0f, -0.08832942f, 0.23389032f, 0.76027237f,
   0.58751830f, 0.0f, -0.11430184f, 0.0f, 0.0f };
__constant__ float c_H0B[10] = {
   0.0f, 0.0f, -0.11430184f, 0.0f, 0.58751830f,
   0.76027237f, 0.23389032f, -0.08832942f, 0.0f, 0.03516384f };
__constant__ float c_H1A[10] = {
   0.0f, 0.0f, -0.11430184f, 0.0f, 0.58751830f,
  -0.76027237f, 0.23389032f, 0.08832942f, 0.0f, -0.03516384f };
__constant__ float c_H1B[10] = {
  -0.03516384f, 0.0f, 0.08832942f, 0.23389032f, -0.76027237f,
   0.58751830f, 0.0f, -0.11430184f, 0.0f, 0.0f };

// ---------------- scratch: interleaved (r,i) bandpass ----------------
__device__ float2 g_bp[(size_t)JLEV * ROWS * NN];

// ---------------- packed f32x2 helpers ----------------
__device__ __forceinline__ ull pack2(float x, float y) {
  ull r; asm("mov.b64 %0, {%1, %2};" : "=l"(r) : "f"(x), "f"(y)); return r;
}
__device__ __forceinline__ void unpack2(ull v, float& x, float& y) {
  asm("mov.b64 {%0, %1}, %2;" : "=f"(x), "=f"(y) : "l"(v));
}
__device__ __forceinline__ ull ffma2(ull a, ull b, ull c) {
  ull d; asm("fma.rn.f32x2 %0, %1, %2, %3;" : "=l"(d) : "l"(a), "l"(b), "l"(c));
  return d;
}

// ---------------- kernel 1: undecimated dual-tree CWT ----------------
#define TILE_W 2048
#define HALO   80
#define EXT    (TILE_W + 2*HALO)   // 2208

template<int D, int M>
__device__ __forceinline__ void tree_level(
    const float* la, const float* lb,
    float* la_n, float* lb_n,
    float2* __restrict__ bp)
{
  const int PAD = (D * 9) / 2;
  for (int i = threadIdx.x; i < TILE_W; i += 256) {
    const int s = HALO + i;
    float ar = 0.f, ai = 0.f;
#pragma unroll
    for (int k = 0; k < 10; k++) {
      ar = fmaf(c_H1A[k], la[s + D*k - PAD], ar);
      ai = fmaf(c_H1B[k], lb[s + D*k - PAD], ai);
    }
    bp[i] = make_float2(ar, ai);
  }
  if (la_n != nullptr) {
    for (int i = threadIdx.x; i < TILE_W + 2*M; i += 256) {
      const int s = HALO - M + i;
      float a = 0.f, b = 0.f;
#pragma unroll
      for (int k = 0; k < 10; k++) {
        a = fmaf(c_H0A[k], la[s + D*k - PAD], a);
        b = fmaf(c_H0B[k], lb[s + D*k - PAD], b);
      }
      la_n[s] = a; lb_n[s] = b;
    }
  }
}

__global__ __launch_bounds__(256) void udtcwt_kernel(const float* __restrict__ x)
{
  __shared__ float sA[EXT], sB[EXT], sC[EXT], sD[EXT];
  const int row = blockIdx.y;
  const int t0  = blockIdx.x * TILE_W;
  const float* xr = x + (size_t)row * NN;

  for (int s = threadIdx.x; s < EXT; s += 256) {
    const int g = t0 - HALO + s;
    sA[s] = (g >= 0 && g < NN) ? xr[g] : 0.f;
  }
  __syncthreads();

  // level 0: 13-tap near_sym_b, both trees identical
  {
    float2* outp = g_bp + ((size_t)(0*ROWS + row)) * NN + t0;
    for (int i = threadIdx.x; i < TILE_W; i += 256) {
      const int s = HALO + i;
      float acc = 0.f;
#pragma unroll
      for (int k = 0; k < 13; k++) acc = fmaf(c_H1O[k], sA[s + k - 6], acc);
      outp[i] = make_float2(acc, acc);
    }
    for (int i = threadIdx.x; i < TILE_W + 2*68; i += 256) {
      const int s = HALO - 68 + i;
      float acc = 0.f;
#pragma unroll
      for (int k = 0; k < 13; k++) acc = fmaf(c_H0O[k], sA[s + k - 6], acc);
      sB[s] = acc;
    }
  }
  __syncthreads();

  tree_level<1, 63>(sB, sB, sC, sD, g_bp + ((size_t)(1*ROWS + row))*NN + t0);
  __syncthreads();
  tree_level<2, 54>(sC, sD, sA, sB, g_bp + ((size_t)(2*ROWS + row))*NN + t0);
  __syncthreads();
  tree_level<4, 36>(sA, sB, sC, sD, g_bp + ((size_t)(3*ROWS + row))*NN + t0);
  __syncthreads();
  tree_level<8, 0>(sC, sD, (float*)nullptr, (float*)nullptr,
                   g_bp + ((size_t)(4*ROWS + row))*NN + t0);
}

// ---------------- kernel 2: all scales, one launch ----------------
#define TOX    1024
#define ULEN   (4*TOX + 33)      // 4129
#define UWORDS 4160              // padded s_u size (multiple of 32)
#define BPF2   4360              // worst-case D*SPP (D=8)

// shared memory byte offsets (dynamic smem)
#define OFF_BP 0
#define OFF_U  (BPF2 * 8)                 // 34880
#define OFF_W  (OFF_U + UWORDS * 4)       // 51520
#define OFF_G  (OFF_W + QQ * TT * 8)      // 52480
#define OFF_A  (OFF_G + 40 * 4)           // 52640
#define SMEM_BYTES (OFF_A + 32)           // 52672

// word-granular swizzle of s_u matching float4-granular swz4(f)=f^((f>>3)&7)
__device__ __forceinline__ int swzw(int i) { return i ^ (((i >> 5) & 7) << 2); }

template<int LD>
__device__ __forceinline__ void scatter_body(
    char* smem, int j, int row, int o0,
    const float* __restrict__ conv_w, const float* __restrict__ roots,
    const float* __restrict__ beta_p, float* __restrict__ out)
{
  constexpr int D    = 1 << LD;
  constexpr int SU   = (ULEN + D - 1) / D;       // u's per phase
  constexpr int CP   = (SU + 3) / 4;             // 4-u chunks per phase
  constexpr int CHK  = D * CP;
  constexpr int SLEN = 4 * CP + 18;
  constexpr int SPP  = ((SLEN + 15) & ~15) | 1;  // stride ≡ 1 (mod 16)

  float2* s_bp    = (float2*)(smem + OFF_BP);
  float*  s_u     = (float*) (smem + OFF_U);
  ull*    s_w2    = (ull*)   (smem + OFF_W);
  float*  s_g     = (float*) (smem + OFF_G);
  float*  s_alpha = (float*) (smem + OFF_A);

  const int b = row >> 2, c = row & 3;
  const float inv_scale = exp2f(-0.5f * (float)j);
  const float beta = beta_p[0];
  const int tid  = threadIdx.x;
  const int tmin = 4 * o0 - 18;
  const int pmin = tmin - 7 * D;

  const float2* bp = g_bp + ((size_t)(j * ROWS + row)) * NN;

  // ---- fill phase-separated bp tile ----
  for (int i = tid; i < D * SPP; i += 256) {
    const int p = i & (D - 1), s = i >> LD;
    const int idx = p * SPP + s;
    const int ii = (LD == 0) ? (idx ^ ((idx >> 4) & 3)) : idx;
    const int gi = pmin + i;
    s_bp[ii] = (gi >= 0 && gi < NN) ? bp[gi] : make_float2(0.f, 0.f);
  }
  if (tid < 37) {                      // composite /4 downsample filter
    const int m = tid;
    float acc = 0.f;
    for (int k = 0; k < 13; k++) {
      const int kp = m - 2 * k;
      if (kp >= 0 && kp < 13) acc += c_H0O[k] * c_H0O[kp];
    }
    s_g[m] = acc;
  }
  for (int i = tid; i < QQ * TT; i += 256) {
    const int q = i / TT, k = i % TT;
    const float wv = conv_w[(size_t)(j * CQ + c * QQ + q) * TT + k];
    s_w2[i] = pack2(wv, wv);
  }
  if (tid < QQ) {
    const float rt = roots[j * CQ + c * QQ + tid];
    s_alpha[tid] = 1.f / (1.f + __expf(-rt));
  }
  __syncthreads();

  for (int q = 0; q < QQ; q++) {
    const ull* wq = s_w2 + q * TT;
    const float alpha = s_alpha[q];

    // ---- u stage: 4 consecutive-in-phase u's per chunk ----
    for (int m = tid; m < CHK; m += 256) {
      const int p = m & (D - 1), cc = m >> LD;
      const int base = p * SPP + 4 * cc;
      ull v[18];
#pragma unroll
      for (int t = 0; t < 18; t++) {
        const int idx = base + t;
        const int ii = (LD == 0) ? (idx ^ ((idx >> 4) & 3)) : idx;
        const float2 f = s_bp[ii];
        v[t] = pack2(f.x, f.y);
      }
      ull a0 = pack2(0.f, 0.f), a1 = a0, a2 = a0, a3 = a0;
#pragma unroll
      for (int k = 0; k < TT; k++) {
        const ull wk = wq[k];
        a0 = ffma2(wk, v[k],     a0);
        a1 = ffma2(wk, v[k + 1], a1);
        a2 = ffma2(wk, v[k + 2], a2);
        a3 = ffma2(wk, v[k + 3], a3);
      }
      const int ui0 = p + ((4 * cc) << LD);
#pragma unroll
      for (int r = 0; r < 4; r++) {
        const ull av = (r == 0) ? a0 : (r == 1) ? a1 : (r == 2) ? a2 : a3;
        const int ui = ui0 + (r << LD);
        if (ui < ULEN) {
          float rr, ii2; unpack2(av, rr, ii2);
          const int t = tmin + ui;
          float u = 0.f;
          if (t >= 0 && t < NN) {
            const float hyp = sqrtf(fmaf(rr, rr, ii2 * ii2)) * inv_scale;
            u = exp2f(alpha * __log2f(hyp + beta));
          }
          s_u[swzw(ui)] = u;
        }
      }
    }
    __syncthreads();

    // ---- down stage: 37-tap stride-4, 4 consecutive outputs/thread ----
    {
      const float4* su4 = (const float4*)s_u;
      const int f0 = 4 * tid;
      float a[52];
#pragma unroll
      for (int mm = 0; mm < 13; mm++) {
        int f = f0 + mm; f ^= (f >> 3) & 7;
        const float4 qv = su4[f];
        a[4*mm] = qv.x; a[4*mm+1] = qv.y; a[4*mm+2] = qv.z; a[4*mm+3] = qv.w;
      }
      float acc0 = 0.f, acc1 = 0.f, acc2 = 0.f, acc3 = 0.f;
#pragma unroll
      for (int mm = 0; mm < 37; mm++) {
        const float gv = s_g[mm];
        acc0 = fmaf(gv, a[mm],      acc0);
        acc1 = fmaf(gv, a[mm + 4],  acc1);
        acc2 = fmaf(gv, a[mm + 8],  acc2);
        acc3 = fmaf(gv, a[mm + 12], acc3);
      }
      float4 o; o.x = acc0; o.y = acc1; o.z = acc2; o.w = acc3;
      float* dst = out + ((size_t)(b * OUTCH + j * CQ + c * QQ + q)) * OUTN
                       + o0 + 4 * tid;
      *reinterpret_cast<float4*>(dst) = o;
    }
    __syncthreads();
  }
}

__global__ __launch_bounds__(256) void scatter_all(
    const float* __restrict__ conv_w, const float* __restrict__ roots,
    const float* __restrict__ beta_p, float* __restrict__ out)
{
  extern __shared__ char smem[];
  const int j   = blockIdx.z;
  const int row = blockIdx.y;
  const int o0  = blockIdx.x * TOX;

  if (j <= 1)      scatter_body<0>(smem, j, row, o0, conv_w, roots, beta_p, out);
  else if (j == 2) scatter_body<1>(smem, j, row, o0, conv_w, roots, beta_p, out);
  else if (j == 3) scatter_body<2>(smem, j, row, o0, conv_w, roots, beta_p, out);
  else             scatter_body<3>(smem, j, row, o0, conv_w, roots, beta_p, out);
}

// ---------------- launch ----------------
extern "C" void kernel_launch(void* const* d_in, const int* in_sizes, int n_in,
                              void* d_out, int out_size)
{
  const float* x      = (const float*)d_in[0];
  const float* conv_w = (const float*)d_in[1];
  const float* roots  = (const float*)d_in[2];
  const float* beta   = (const float*)d_in[3];
  float* out = (float*)d_out;

  cudaFuncSetAttribute(scatter_all,
      cudaFuncAttributeMaxDynamicSharedMemorySize, SMEM_BYTES);

  dim3 gW(NN / TILE_W, ROWS);                 // 32 x 16
  udtcwt_kernel<<<gW, 256>>>(x);

  dim3 gS(OUTN / TOX, ROWS, JLEV);            // 16 x 16 x 5 = 1280 CTAs
  scatter_all<<<gS, 256, SMEM_BYTES>>>(conv_w, roots, beta, out);
}